// round 15
// baseline (speedup 1.0000x reference)
#include <cuda_runtime.h>
#include <cuda_fp16.h>
#include <math.h>
#include <cstdint>

#define B_ 4
#define T_ 1024
#define C_ 256
#define D_ 256
#define H_ 512
#define NH_ 8
#define HD_ 64
#define INTER_ 2048
#define L_ 4
#define M_ (B_*T_)          // 4096 rows

// ---------------- weight scratch offsets (elements, fp16) ----------------
#define OFF_EMB   0u
#define OFF_PROJ  65536u
#define OFF_LAYER 196608u
#define PER_LAYER 3145728u
#define OFF_QKV(l)  (OFF_LAYER + (l)*PER_LAYER)
#define OFF_O(l)    (OFF_LAYER + (l)*PER_LAYER + 786432u)
#define OFF_UP(l)   (OFF_LAYER + (l)*PER_LAYER + 1048576u)
#define OFF_DOWN(l) (OFF_LAYER + (l)*PER_LAYER + 2097152u)
#define WT_TOTAL (OFF_LAYER + 4u*PER_LAYER)   // 12,779,520

__device__ __half g_wth[WT_TOTAL];   // weight hi (fp16)
__device__ __half g_wtl[WT_TOTAL];   // weight lo (fp16)

__device__ __half g_sp[M_*C_];       // spikes fp16
__device__ __half g_e[M_*D_];        // embed intermediate fp16
__device__ __half g_h[M_*H_];        // LN output fp16
__device__ __half g_o[M_*H_];        // attn output fp16
__device__ __half g_u[M_*INTER_];    // MLP intermediate fp16
__device__ float g_q[M_*H_], g_k[M_*H_], g_v[M_*H_];
__device__ float g_qkvb[L_*1536];

// ---------------- helpers ----------------
__device__ __forceinline__ float gelu_f(float x) {
    return 0.5f * x * (1.0f + erff(x * 0.70710678118654752440f));
}
__device__ __forceinline__ void split_h(float x, __half& h, __half& l) {
    h = __float2half_rn(x);
    l = __float2half_rn(x - __half2float(h));
}
__device__ __forceinline__ uint32_t smem_u32(const void* p) {
    uint32_t a;
    asm("{ .reg .u64 t; cvta.to.shared.u64 t, %1; cvt.u32.u64 %0, t; }" : "=r"(a) : "l"(p));
    return a;
}

#define CP16(dst, src) \
    asm volatile("cp.async.cg.shared.global [%0], [%1], 16;" :: "r"(dst), "l"(src))
#define CPCOMMIT() asm volatile("cp.async.commit_group;" ::: "memory")
#define CPWAIT(n)  asm volatile("cp.async.wait_group %0;" :: "n"(n) : "memory")

#define LDSM4(r, a) \
    asm volatile("ldmatrix.sync.aligned.m8n8.x4.shared.b16 {%0,%1,%2,%3}, [%4];" \
        : "=r"((r)[0]), "=r"((r)[1]), "=r"((r)[2]), "=r"((r)[3]) : "r"(a))

// fp16 inputs, fp32 accumulate
#define MMA16816(c, a, b0v, b1v) \
    asm("mma.sync.aligned.m16n8k16.row.col.f32.f16.f16.f32 " \
        "{%0,%1,%2,%3}, {%4,%5,%6,%7}, {%8,%9}, {%0,%1,%2,%3};" \
        : "+f"((c)[0]), "+f"((c)[1]), "+f"((c)[2]), "+f"((c)[3]) \
        : "r"((a)[0]), "r"((a)[1]), "r"((a)[2]), "r"((a)[3]), "r"(b0v), "r"(b1v))

// smem tile layout: row stride 64B (32 fp16), XOR swizzle on 16B columns
__device__ __forceinline__ uint32_t tileoff(int row, int c) {
    return (uint32_t)(row * 64 + ((c ^ ((row >> 1) & 3)) << 4));
}

// ---------------- fused transpose+split of ALL weights (+bias pack) -------
__global__ __launch_bounds__(256) void transpose_split_all(
    const float* __restrict__ embed_w, const float* __restrict__ proj_w,
    const float* __restrict__ Wq, const float* __restrict__ Wk,
    const float* __restrict__ Wv, const float* __restrict__ Wo,
    const float* __restrict__ up_w, const float* __restrict__ down_w,
    const float* __restrict__ bq, const float* __restrict__ bk,
    const float* __restrict__ bv,
    __half* __restrict__ Th, __half* __restrict__ Tl,
    float* __restrict__ qkvb)
{
    const int seg = blockIdx.y;
    if (seg == 26) {
        int i = blockIdx.x * 256 + threadIdx.x;
        if (i < L_ * 1536) {
            int l = i / 1536, j = i % 1536;
            float v = (j < 512) ? bq[l * 512 + j]
                    : (j < 1024) ? bk[l * 512 + j - 512] : bv[l * 512 + j - 1024];
            qkvb[i] = v;
        }
        return;
    }
    const float* src; uint32_t dstoff; int K, N, l;
    if (seg == 0)       { src = embed_w; dstoff = OFF_EMB;  K = C_; N = D_; }
    else if (seg == 1)  { src = proj_w;  dstoff = OFF_PROJ; K = D_; N = H_; }
    else if (seg < 6)   { l = seg - 2;  src = Wq + (size_t)l * H_ * H_; dstoff = OFF_QKV(l);            K = H_; N = H_; }
    else if (seg < 10)  { l = seg - 6;  src = Wk + (size_t)l * H_ * H_; dstoff = OFF_QKV(l) + 262144u;  K = H_; N = H_; }
    else if (seg < 14)  { l = seg - 10; src = Wv + (size_t)l * H_ * H_; dstoff = OFF_QKV(l) + 524288u;  K = H_; N = H_; }
    else if (seg < 18)  { l = seg - 14; src = Wo + (size_t)l * H_ * H_; dstoff = OFF_O(l);              K = H_; N = H_; }
    else if (seg < 22)  { l = seg - 18; src = up_w   + (size_t)l * H_ * INTER_; dstoff = OFF_UP(l);   K = H_;     N = INTER_; }
    else                { l = seg - 22; src = down_w + (size_t)l * INTER_ * H_; dstoff = OFF_DOWN(l); K = INTER_; N = H_; }

    const int tiles_x = N >> 5, tiles_y = K >> 5;
    const int tile = blockIdx.x;
    if (tile >= tiles_x * tiles_y) return;
    const int n0 = (tile % tiles_x) * 32, k0 = (tile / tiles_x) * 32;

    __shared__ float t[32][33];
    const int tx = threadIdx.x & 31, ty = threadIdx.x >> 5;
    #pragma unroll
    for (int i = ty; i < 32; i += 8)
        t[i][tx] = src[(size_t)(k0 + i) * N + n0 + tx];
    __syncthreads();
    #pragma unroll
    for (int i = ty; i < 32; i += 8) {
        float v = t[tx][i];
        __half h, lo; split_h(v, h, lo);
        size_t o = dstoff + (size_t)(n0 + i) * K + k0 + tx;
        Th[o] = h; Tl[o] = lo;
    }
}

// ---------------- elementwise fp16 convert (spikes) ----------------
__global__ __launch_bounds__(256) void tohalf_kernel(
    const float* __restrict__ x, __half* __restrict__ h, int n)
{
    int i = blockIdx.x * 256 + threadIdx.x;
    if (i < n) h[i] = __float2half_rn(x[i]);
}

// ---------------- HMMA GEMM: C = epi(A @ B^T + bias) ----------------
// A single fp16 [M,K]; B hi/lo fp16 [N,K]. 2 passes A*Bh + A*Bl, fp32 acc.
// tile 64x64, BK=32, 3-stage cp.async, 4 warps (warp 32x32, 2x2), 6 CTAs/SM.
// EPI_QKV applies RoPE in the epilogue (tile = exactly one head).
#define EPI_GELU  0
#define EPI_PLAIN 1
#define EPI_RESID 2
#define EPI_QKV   3
// stage: A 4096, BH 4096, BL 4096 = 12288; 3 stages = 36864
#define STG 12288
#define OFF_BH 4096
#define OFF_BL 8192
#define GEMM_SMEM (3*STG)   // 36864; epilogue reuses 64*65*4 = 16640

__global__ __launch_bounds__(128, 6) void hmma_gemm(
    const __half* __restrict__ A,
    const __half* __restrict__ Bh, const __half* __restrict__ Bl,
    const float* __restrict__ bias, const float* __restrict__ resid,
    const int* __restrict__ ts,
    float* __restrict__ outf, __half* __restrict__ outh,
    float* __restrict__ q, float* __restrict__ k, float* __restrict__ v,
    int N, int K, int epi)
{
    extern __shared__ __align__(1024) char smc[];
    const uint32_t sbase = smem_u32(smc);
    const int tid = threadIdx.x, wid = tid >> 5, lane = tid & 31;
    const int n0 = blockIdx.x * 64, m0 = blockIdx.y * 64;
    const int m0w = (wid & 1) * 32, n0w = (wid >> 1) * 32;

    float acc[2][4][4];
    #pragma unroll
    for (int a = 0; a < 2; a++)
        #pragma unroll
        for (int b = 0; b < 4; b++)
            #pragma unroll
            for (int c = 0; c < 4; c++) acc[a][b][c] = 0.f;

    // cp.async mapping: 64 rows x 4 16B-cols per matrix; 128 threads -> 2 each
    const int grow = tid >> 1, gc = (tid & 1) * 2;
    const __half* pA  = A  + (size_t)(m0 + grow) * K + gc * 8;
    const __half* pBh = Bh + (size_t)(n0 + grow) * K + gc * 8;
    const __half* pBl = Bl + (size_t)(n0 + grow) * K + gc * 8;
    const uint32_t o0 = tileoff(grow, gc);
    const uint32_t o1 = tileoff(grow, gc + 1);

    auto issue = [&](int chunk, uint32_t sb) {
        const int kc = chunk * 32;
        CP16(sb + o0,            pA  + kc);
        CP16(sb + o1,            pA  + kc + 8);
        CP16(sb + o0 + OFF_BH,   pBh + kc);
        CP16(sb + o1 + OFF_BH,   pBh + kc + 8);
        CP16(sb + o0 + OFF_BL,   pBl + kc);
        CP16(sb + o1 + OFF_BL,   pBl + kc + 8);
    };

    const int nk = K >> 5;
    issue(0, sbase);            CPCOMMIT();
    issue(1, sbase + STG);      CPCOMMIT();

    int stage_c = 0;
    for (int t = 0; t < nk; t++) {
        if (t + 1 < nk) { CPWAIT(1); } else { CPWAIT(0); }
        __syncthreads();
        if (t + 2 < nk) {
            int sp = stage_c + 2; if (sp >= 3) sp -= 3;
            issue(t + 2, sbase + sp * STG);
            CPCOMMIT();
        }

        const uint32_t sb = sbase + stage_c * STG;
        #pragma unroll
        for (int ks = 0; ks < 2; ks++) {
            const int kcol = ks * 2 + (lane >> 4);
            uint32_t ar[2][4], bh4[2][4], bl4[2][4];
            #pragma unroll
            for (int mt = 0; mt < 2; mt++) {
                int row = m0w + mt * 16 + (lane & 15);
                LDSM4(ar[mt], sb + tileoff(row, kcol));
            }
            #pragma unroll
            for (int g = 0; g < 2; g++) {
                int row = n0w + g * 16 + (lane & 15);
                uint32_t a = sb + OFF_BH + tileoff(row, kcol);
                LDSM4(bh4[g], a);
                LDSM4(bl4[g], a + (OFF_BL - OFF_BH));
            }
            #pragma unroll
            for (int mt = 0; mt < 2; mt++)
                #pragma unroll
                for (int nt = 0; nt < 4; nt++) {
                    int g = nt >> 1, s = nt & 1;
                    MMA16816(acc[mt][nt], ar[mt], bh4[g][s], bh4[g][s + 2]);
                    MMA16816(acc[mt][nt], ar[mt], bl4[g][s], bl4[g][s + 2]);
                }
        }
        if (++stage_c == 3) stage_c = 0;
    }
    __syncthreads();

    // ---- epilogue stage 1: regs -> padded smem [64][65] ----
    float* ep = (float*)smc;
    {
        const int r0 = lane >> 2, cc = (lane & 3) * 2;
        #pragma unroll
        for (int mt = 0; mt < 2; mt++)
            #pragma unroll
            for (int nt = 0; nt < 4; nt++) {
                int row = m0w + mt * 16 + r0;
                int col = n0w + nt * 8 + cc;
                ep[row * 65 + col]           = acc[mt][nt][0];
                ep[row * 65 + col + 1]       = acc[mt][nt][1];
                ep[(row + 8) * 65 + col]     = acc[mt][nt][2];
                ep[(row + 8) * 65 + col + 1] = acc[mt][nt][3];
            }
    }
    __syncthreads();

    // ---- epilogue stage 2: smem -> gmem ----
    if (epi == EPI_QKV) {
        // tile covers exactly one head: n0 multiple of 64, HD=64
        const int sel = n0 >> 9, head = (n0 & 511) >> 6;
        float* dst = (sel == 0) ? q : (sel == 1) ? k : v;
        const int d = tid & 31;   // invariant across loop (128 % 32 == 0)
        float invf = 0.f;
        if (sel < 2) invf = powf(10000.f, -(float)d * (1.0f / 32.0f));
        for (int p = tid; p < 64 * 32; p += 128) {
            int m = p >> 5;
            int mg = m0 + m, b = mg >> 10, tt = mg & 1023;
            float v0 = ep[m * 65 + d]      + bias[n0 + d];
            float v1 = ep[m * 65 + d + 32] + bias[n0 + d + 32];
            size_t oi = (((size_t)(b * NH_ + head)) * T_ + tt) * (size_t)HD_ + d;
            if (sel < 2) {
                float ang = (float)ts[b * T_ + tt] * invf, s, c;
                sincosf(ang, &s, &c);
                dst[oi]      = v0 * c - v1 * s;
                dst[oi + 32] = v1 * c + v0 * s;
            } else {
                dst[oi] = v0; dst[oi + 32] = v1;
            }
        }
    } else {
        for (int p = tid; p < 64 * 32; p += 128) {
            int m = p >> 5, np = (p & 31) << 1;
            int mg = m0 + m, n = n0 + np;
            float v0 = ep[m * 65 + np]     + bias[n];
            float v1 = ep[m * 65 + np + 1] + bias[n + 1];
            if (epi == EPI_GELU) {
                v0 = gelu_f(v0); v1 = gelu_f(v1);
                __half2 hp; hp.x = __float2half_rn(v0); hp.y = __float2half_rn(v1);
                *(__half2*)(outh + (size_t)mg * N + n) = hp;
            } else if (epi == EPI_PLAIN) {
                float2 o; o.x = v0; o.y = v1;
                *(float2*)(outf + (size_t)mg * N + n) = o;
            } else { // EPI_RESID
                float2 rr = *(const float2*)(resid + (size_t)mg * N + n);
                float2 o; o.x = v0 + rr.x; o.y = v1 + rr.y;
                *(float2*)(outf + (size_t)mg * N + n) = o;
            }
        }
    }
}

// ---------------- LayerNorm over H=512 -> fp16 ----------------
__global__ __launch_bounds__(128) void ln_kernel(
    const float* __restrict__ x, const float* __restrict__ g,
    const float* __restrict__ b, __half* __restrict__ oh)
{
    const int r = blockIdx.x;
    const int tid = threadIdx.x;
    const float* row = x + (size_t)r * H_;
    float4 v = *(const float4*)(row + tid * 4);
    float s = v.x + v.y + v.z + v.w;
    float q = v.x * v.x + v.y * v.y + v.z * v.z + v.w * v.w;
    __shared__ float ss[128], sq[128];
    ss[tid] = s; sq[tid] = q;
    __syncthreads();
    #pragma unroll
    for (int st = 64; st > 0; st >>= 1) {
        if (tid < st) { ss[tid] += ss[tid + st]; sq[tid] += sq[tid + st]; }
        __syncthreads();
    }
    float mean = ss[0] * (1.0f / H_);
    float var  = sq[0] * (1.0f / H_) - mean * mean;
    float inv  = rsqrtf(var + 1e-5f);
    float4 gg = *(const float4*)(g + tid * 4);
    float4 bb = *(const float4*)(b + tid * 4);
    float o0 = (v.x - mean) * inv * gg.x + bb.x;
    float o1 = (v.y - mean) * inv * gg.y + bb.y;
    float o2 = (v.z - mean) * inv * gg.z + bb.z;
    float o3 = (v.w - mean) * inv * gg.w + bb.w;
    size_t o = (size_t)r * H_ + tid * 4;
    __half2 p0; p0.x = __float2half_rn(o0); p0.y = __float2half_rn(o1);
    __half2 p1; p1.x = __float2half_rn(o2); p1.y = __float2half_rn(o3);
    *(__half2*)(oh + o)     = p0;
    *(__half2*)(oh + o + 2) = p1;
}

// ---------------- Banded attention (fp32, outputs fp16) ----------------
#define TQ 64
#define SPAN 192
#define KT_STRIDE 196
#define ATTN_SMEM ((64*64 + 64*KT_STRIDE + SPAN*64 + 8*SPAN + SPAN) * 4)

__global__ __launch_bounds__(256) void attn_kernel(
    const float* __restrict__ q, const float* __restrict__ k,
    const float* __restrict__ v, const int* __restrict__ smask,
    __half* __restrict__ o_h)
{
    extern __shared__ __align__(16) float sm[];
    float* Qs = sm;                       // [64][64]
    float* Kt = Qs + 64 * 64;             // [64][KT_STRIDE] transposed K
    float* Vs = Kt + 64 * KT_STRIDE;      // [SPAN][64]
    float* Ps = Vs + SPAN * 64;           // [8 warps][SPAN]
    float* Km = Ps + 8 * SPAN;            // [SPAN] mask add

    const int tid = threadIdx.x;
    const int qb = blockIdx.x, hh = blockIdx.y, b = blockIdx.z;
    const int i0 = qb * TQ;
    const int j0 = i0 - 128;
    const float* qb_ = q + ((size_t)(b * NH_ + hh) * T_) * HD_;
    const float* kb_ = k + ((size_t)(b * NH_ + hh) * T_) * HD_;
    const float* vb_ = v + ((size_t)(b * NH_ + hh) * T_) * HD_;

    for (int idx = tid; idx < 64 * 16; idx += 256) {
        int r = idx >> 4, c4 = (idx & 15) << 2;
        *(float4*)(Qs + r * 64 + c4) =
            *(const float4*)(qb_ + (size_t)(i0 + r) * HD_ + c4);
    }
    for (int idx = tid; idx < SPAN * 16; idx += 256) {
        int r = idx >> 4, c4 = (idx & 15) << 2;
        int j = j0 + r;
        float4 kv = make_float4(0.f, 0.f, 0.f, 0.f);
        float4 vv = make_float4(0.f, 0.f, 0.f, 0.f);
        if (j >= 0) {
            kv = *(const float4*)(kb_ + (size_t)j * HD_ + c4);
            vv = *(const float4*)(vb_ + (size_t)j * HD_ + c4);
        }
        Kt[(c4 + 0) * KT_STRIDE + r] = kv.x;
        Kt[(c4 + 1) * KT_STRIDE + r] = kv.y;
        Kt[(c4 + 2) * KT_STRIDE + r] = kv.z;
        Kt[(c4 + 3) * KT_STRIDE + r] = kv.w;
        *(float4*)(Vs + r * 64 + c4) = vv;
    }
    for (int idx = tid; idx < SPAN; idx += 256) {
        int j = j0 + idx;
        Km[idx] = (j >= 0 && smask[b * T_ + j] != 0) ? 0.f : -1e30f;
    }
    __syncthreads();

    const int w = tid >> 5, l = tid & 31;
    for (int r = 0; r < 8; r++) {
        int qq = w * 8 + r;
        int i = i0 + qq;
        float s0 = 0.f, s1 = 0.f, s2 = 0.f, s3 = 0.f, s4 = 0.f, s5 = 0.f;
        const float* qrow = Qs + qq * 64;
        #pragma unroll 8
        for (int d = 0; d < 64; d++) {
            float qv = qrow[d];
            const float* kr = Kt + d * KT_STRIDE + l;
            s0 += qv * kr[0];   s1 += qv * kr[32];  s2 += qv * kr[64];
            s3 += qv * kr[96];  s4 += qv * kr[128]; s5 += qv * kr[160];
        }
        float sv[6];
        float sc[6] = {s0, s1, s2, s3, s4, s5};
        float mx = -1e30f;
        #pragma unroll
        for (int c = 0; c < 6; c++) {
            int jj = c * 32 + l;
            bool inband = (jj >= qq) && (jj <= qq + 128);
            sv[c] = inband ? (sc[c] * 0.125f + Km[jj]) : -1e30f;
            mx = fmaxf(mx, sv[c]);
        }
        #pragma unroll
        for (int st = 16; st; st >>= 1)
            mx = fmaxf(mx, __shfl_xor_sync(0xffffffffu, mx, st));
        float e[6], sum = 0.f;
        #pragma unroll
        for (int c = 0; c < 6; c++) { e[c] = __expf(sv[c] - mx); sum += e[c]; }
        #pragma unroll
        for (int st = 16; st; st >>= 1)
            sum += __shfl_xor_sync(0xffffffffu, sum, st);
        float invs = 1.0f / sum;
        #pragma unroll
        for (int c = 0; c < 6; c++)
            Ps[w * SPAN + c * 32 + l] = e[c] * invs;
        __syncwarp();

        float ax = 0.f, ay = 0.f;
        const float* pp = Ps + w * SPAN;
        const int jend = qq + 128;
        for (int jj = qq; jj <= jend; jj++) {
            float pj = pp[jj];
            float2 vv = *(const float2*)(Vs + jj * 64 + (l << 1));
            ax += pj * vv.x; ay += pj * vv.y;
        }
        size_t oi = (((size_t)b * T_ + i) * NH_ + hh) * (size_t)HD_ + (l << 1);
        __half2 hp; hp.x = __float2half_rn(ax); hp.y = __float2half_rn(ay);
        *(__half2*)(o_h + oi) = hp;
        __syncwarp();
    }
}

// ---------------- launcher ----------------
extern "C" void kernel_launch(void* const* d_in, const int* in_sizes, int n_in,
                              void* d_out, int out_size)
{
    const float* spikes   = (const float*)d_in[0];
    const int*   smask    = (const int*)  d_in[1];
    const int*   ts       = (const int*)  d_in[2];
    const float* embed_w  = (const float*)d_in[3];
    const float* embed_b  = (const float*)d_in[4];
    const float* proj_w   = (const float*)d_in[5];
    const float* proj_b   = (const float*)d_in[6];
    const float* ln1_g    = (const float*)d_in[7];
    const float* ln1_b    = (const float*)d_in[8];
    const float* Wq       = (const float*)d_in[9];
    const float* bq       = (const float*)d_in[10];
    const float* Wk       = (const float*)d_in[11];
    const float* bk       = (const float*)d_in[12];
    const float* Wv       = (const float*)d_in[13];
    const float* bv       = (const float*)d_in[14];
    const float* Wo       = (const float*)d_in[15];
    const float* bo       = (const float*)d_in[16];
    const float* ln2_g    = (const float*)d_in[17];
    const float* ln2_b    = (const float*)d_in[18];
    const float* up_w     = (const float*)d_in[19];
    const float* up_b     = (const float*)d_in[20];
    const float* down_w   = (const float*)d_in[21];
    const float* down_b   = (const float*)d_in[22];
    float* x = (float*)d_out;

    __half *wth, *wtl, *sp, *e, *h, *o, *u;
    float *qp, *kp, *vp, *qkvb;
    cudaGetSymbolAddress((void**)&wth, g_wth);
    cudaGetSymbolAddress((void**)&wtl, g_wtl);
    cudaGetSymbolAddress((void**)&sp,  g_sp);
    cudaGetSymbolAddress((void**)&e,   g_e);
    cudaGetSymbolAddress((void**)&h,   g_h);
    cudaGetSymbolAddress((void**)&o,   g_o);
    cudaGetSymbolAddress((void**)&u,   g_u);
    cudaGetSymbolAddress((void**)&qp,  g_q);
    cudaGetSymbolAddress((void**)&kp,  g_k);
    cudaGetSymbolAddress((void**)&vp,  g_v);
    cudaGetSymbolAddress((void**)&qkvb, g_qkvb);

    cudaFuncSetAttribute(attn_kernel,
        cudaFuncAttributeMaxDynamicSharedMemorySize, ATTN_SMEM);
    cudaFuncSetAttribute(hmma_gemm,
        cudaFuncAttributeMaxDynamicSharedMemorySize, GEMM_SMEM);

    // ---- preamble: 2 launches ----
    transpose_split_all<<<dim3(1024, 27), 256>>>(
        embed_w, proj_w, Wq, Wk, Wv, Wo, up_w, down_w, bq, bk, bv,
        wth, wtl, qkvb);
    tohalf_kernel<<<(M_ * C_ + 255) / 256, 256>>>(spikes, sp, M_ * C_);

    // ---- embed: e = gelu(spikes @ embed_w + b) -> fp16 ----
    hmma_gemm<<<dim3(D_/64, M_/64), 128, GEMM_SMEM>>>(
        sp, wth + OFF_EMB, wtl + OFF_EMB, embed_b, nullptr, nullptr,
        nullptr, e, nullptr, nullptr, nullptr, D_, C_, EPI_GELU);
    // ---- x = e @ proj_w + b ----
    hmma_gemm<<<dim3(H_/64, M_/64), 128, GEMM_SMEM>>>(
        e, wth + OFF_PROJ, wtl + OFF_PROJ, proj_b, nullptr, nullptr,
        x, nullptr, nullptr, nullptr, nullptr, H_, D_, EPI_PLAIN);

    for (int l = 0; l < L_; l++) {
        ln_kernel<<<M_, 128>>>(x, ln1_g + l * H_, ln1_b + l * H_, h);
        // fused QKV + RoPE: B = [Wq^T; Wk^T; Wv^T]  (N = 1536)
        hmma_gemm<<<dim3(1536/64, M_/64), 128, GEMM_SMEM>>>(
            h, wth + OFF_QKV(l), wtl + OFF_QKV(l), qkvb + l * 1536, nullptr, ts,
            nullptr, nullptr, qp, kp, vp, 1536, H_, EPI_QKV);
        attn_kernel<<<dim3(T_ / TQ, NH_, B_), 256, ATTN_SMEM>>>(qp, kp, vp, smask, o);
        hmma_gemm<<<dim3(H_/64, M_/64), 128, GEMM_SMEM>>>(
            o, wth + OFF_O(l), wtl + OFF_O(l), bo + l * H_, x, nullptr,
            x, nullptr, nullptr, nullptr, nullptr, H_, H_, EPI_RESID);
        ln_kernel<<<M_, 128>>>(x, ln2_g + l * H_, ln2_b + l * H_, h);
        hmma_gemm<<<dim3(INTER_/64, M_/64), 128, GEMM_SMEM>>>(
            h, wth + OFF_UP(l), wtl + OFF_UP(l), up_b + l * INTER_, nullptr, nullptr,
            nullptr, u, nullptr, nullptr, nullptr, INTER_, H_, EPI_GELU);
        hmma_gemm<<<dim3(H_/64, M_/64), 128, GEMM_SMEM>>>(
            u, wth + OFF_DOWN(l), wtl + OFF_DOWN(l), down_b + l * H_, x, nullptr,
            x, nullptr, nullptr, nullptr, nullptr, H_, INTER_, EPI_RESID);
    }
}

// round 17
// speedup vs baseline: 1.0652x; 1.0652x over previous
#include <cuda_runtime.h>
#include <cuda_fp16.h>
#include <math.h>
#include <cstdint>

#define B_ 4
#define T_ 1024
#define C_ 256
#define D_ 256
#define H_ 512
#define NH_ 8
#define HD_ 64
#define INTER_ 2048
#define L_ 4
#define M_ (B_*T_)          // 4096 rows

// ---------------- weight scratch offsets (elements, fp16) ----------------
#define OFF_EMB   0u
#define OFF_PROJ  65536u
#define OFF_LAYER 196608u
#define PER_LAYER 3145728u
#define OFF_QKV(l)  (OFF_LAYER + (l)*PER_LAYER)
#define OFF_O(l)    (OFF_LAYER + (l)*PER_LAYER + 786432u)
#define OFF_UP(l)   (OFF_LAYER + (l)*PER_LAYER + 1048576u)
#define OFF_DOWN(l) (OFF_LAYER + (l)*PER_LAYER + 2097152u)
#define WT_TOTAL (OFF_LAYER + 4u*PER_LAYER)   // 12,779,520

__device__ __half g_wth[WT_TOTAL];   // weight hi (fp16)
__device__ __half g_wtl[WT_TOTAL];   // weight lo (fp16)

__device__ __half g_sp[M_*C_];       // spikes fp16
__device__ __half g_e[M_*D_];        // embed intermediate fp16
__device__ __half g_h[M_*H_];        // LN output fp16
__device__ __half g_o[M_*H_];        // attn output fp16
__device__ __half g_u[M_*INTER_];    // MLP intermediate fp16
__device__ float g_q[M_*H_], g_k[M_*H_], g_v[M_*H_];
__device__ float g_qkvb[L_*1536];

// ---------------- helpers ----------------
__device__ __forceinline__ float gelu_f(float x) {
    return 0.5f * x * (1.0f + erff(x * 0.70710678118654752440f));
}
__device__ __forceinline__ void split_h(float x, __half& h, __half& l) {
    h = __float2half_rn(x);
    l = __float2half_rn(x - __half2float(h));
}
__device__ __forceinline__ uint32_t smem_u32(const void* p) {
    uint32_t a;
    asm("{ .reg .u64 t; cvta.to.shared.u64 t, %1; cvt.u32.u64 %0, t; }" : "=r"(a) : "l"(p));
    return a;
}

#define CP16(dst, src) \
    asm volatile("cp.async.cg.shared.global [%0], [%1], 16;" :: "r"(dst), "l"(src))
#define CPCOMMIT() asm volatile("cp.async.commit_group;" ::: "memory")
#define CPWAIT(n)  asm volatile("cp.async.wait_group %0;" :: "n"(n) : "memory")

#define LDSM4(r, a) \
    asm volatile("ldmatrix.sync.aligned.m8n8.x4.shared.b16 {%0,%1,%2,%3}, [%4];" \
        : "=r"((r)[0]), "=r"((r)[1]), "=r"((r)[2]), "=r"((r)[3]) : "r"(a))

// fp16 inputs, fp32 accumulate
#define MMA16816(c, a, b0v, b1v) \
    asm("mma.sync.aligned.m16n8k16.row.col.f32.f16.f16.f32 " \
        "{%0,%1,%2,%3}, {%4,%5,%6,%7}, {%8,%9}, {%0,%1,%2,%3};" \
        : "+f"((c)[0]), "+f"((c)[1]), "+f"((c)[2]), "+f"((c)[3]) \
        : "r"((a)[0]), "r"((a)[1]), "r"((a)[2]), "r"((a)[3]), "r"(b0v), "r"(b1v))

// smem tile layout: row stride 64B (32 fp16), XOR swizzle on 16B columns
__device__ __forceinline__ uint32_t tileoff(int row, int c) {
    return (uint32_t)(row * 64 + ((c ^ ((row >> 1) & 3)) << 4));
}

// ---------------- fused transpose+split of ALL weights (+bias pack) -------
__global__ __launch_bounds__(256) void transpose_split_all(
    const float* __restrict__ embed_w, const float* __restrict__ proj_w,
    const float* __restrict__ Wq, const float* __restrict__ Wk,
    const float* __restrict__ Wv, const float* __restrict__ Wo,
    const float* __restrict__ up_w, const float* __restrict__ down_w,
    const float* __restrict__ bq, const float* __restrict__ bk,
    const float* __restrict__ bv,
    __half* __restrict__ Th, __half* __restrict__ Tl,
    float* __restrict__ qkvb)
{
    const int seg = blockIdx.y;
    if (seg == 26) {
        int i = blockIdx.x * 256 + threadIdx.x;
        if (i < L_ * 1536) {
            int l = i / 1536, j = i % 1536;
            float v = (j < 512) ? bq[l * 512 + j]
                    : (j < 1024) ? bk[l * 512 + j - 512] : bv[l * 512 + j - 1024];
            qkvb[i] = v;
        }
        return;
    }
    const float* src; uint32_t dstoff; int K, N, l;
    if (seg == 0)       { src = embed_w; dstoff = OFF_EMB;  K = C_; N = D_; }
    else if (seg == 1)  { src = proj_w;  dstoff = OFF_PROJ; K = D_; N = H_; }
    else if (seg < 6)   { l = seg - 2;  src = Wq + (size_t)l * H_ * H_; dstoff = OFF_QKV(l);            K = H_; N = H_; }
    else if (seg < 10)  { l = seg - 6;  src = Wk + (size_t)l * H_ * H_; dstoff = OFF_QKV(l) + 262144u;  K = H_; N = H_; }
    else if (seg < 14)  { l = seg - 10; src = Wv + (size_t)l * H_ * H_; dstoff = OFF_QKV(l) + 524288u;  K = H_; N = H_; }
    else if (seg < 18)  { l = seg - 14; src = Wo + (size_t)l * H_ * H_; dstoff = OFF_O(l);              K = H_; N = H_; }
    else if (seg < 22)  { l = seg - 18; src = up_w   + (size_t)l * H_ * INTER_; dstoff = OFF_UP(l);   K = H_;     N = INTER_; }
    else                { l = seg - 22; src = down_w + (size_t)l * INTER_ * H_; dstoff = OFF_DOWN(l); K = INTER_; N = H_; }

    const int tiles_x = N >> 5, tiles_y = K >> 5;
    const int tile = blockIdx.x;
    if (tile >= tiles_x * tiles_y) return;
    const int n0 = (tile % tiles_x) * 32, k0 = (tile / tiles_x) * 32;

    __shared__ float t[32][33];
    const int tx = threadIdx.x & 31, ty = threadIdx.x >> 5;
    #pragma unroll
    for (int i = ty; i < 32; i += 8)
        t[i][tx] = src[(size_t)(k0 + i) * N + n0 + tx];
    __syncthreads();
    #pragma unroll
    for (int i = ty; i < 32; i += 8) {
        float v = t[tx][i];
        __half h, lo; split_h(v, h, lo);
        size_t o = dstoff + (size_t)(n0 + i) * K + k0 + tx;
        Th[o] = h; Tl[o] = lo;
    }
}

// ---------------- elementwise fp16 convert (spikes) ----------------
__global__ __launch_bounds__(256) void tohalf_kernel(
    const float* __restrict__ x, __half* __restrict__ h, int n)
{
    int i = blockIdx.x * 256 + threadIdx.x;
    if (i < n) h[i] = __float2half_rn(x[i]);
}

// ---------------- HMMA GEMM: C = epi(A @ B^T + bias) ----------------
// A single fp16 [M,K]; B hi/lo fp16 [N,K]. 2 passes A*Bh + A*Bl, fp32 acc.
// tile 128x64, BK=32, 4-stage cp.async (depth-3 prefetch), 8 warps (32x32).
// EPI_QKV applies RoPE in the epilogue (N-tile = exactly one head).
#define EPI_GELU  0
#define EPI_PLAIN 1
#define EPI_RESID 2
#define EPI_QKV   3
// stage: A 8192, BH 4096, BL 4096 = 16384; 4 stages = 65536
#define STG 16384
#define OFF_BH 8192
#define OFF_BL 12288
#define GEMM_SMEM (4*STG)   // 65536; epilogue reuses 128*65*4 = 33280

__global__ __launch_bounds__(256, 3) void hmma_gemm(
    const __half* __restrict__ A,
    const __half* __restrict__ Bh, const __half* __restrict__ Bl,
    const float* __restrict__ bias, const float* __restrict__ resid,
    const int* __restrict__ ts,
    float* __restrict__ outf, __half* __restrict__ outh,
    float* __restrict__ q, float* __restrict__ k, float* __restrict__ v,
    int N, int K, int epi)
{
    extern __shared__ __align__(1024) char smc[];
    const uint32_t sbase = smem_u32(smc);
    const int tid = threadIdx.x, wid = tid >> 5, lane = tid & 31;
    const int n0 = blockIdx.x * 64, m0 = blockIdx.y * 128;
    const int m0w = (wid & 3) * 32, n0w = (wid >> 2) * 32;

    float acc[2][4][4];
    #pragma unroll
    for (int a = 0; a < 2; a++)
        #pragma unroll
        for (int b = 0; b < 4; b++)
            #pragma unroll
            for (int c = 0; c < 4; c++) acc[a][b][c] = 0.f;

    // cp.async mappings: rows x 4 16B-cols (BK=32 fp16 = 64B rows)
    const int arow = tid >> 1, acb = (tid & 1) * 2;      // A: 128 rows, 2 cols/thr
    const int brow = tid >> 2, bc = tid & 3;             // B: 64 rows, 1 col/thr

    const __half* pA  = A  + (size_t)(m0 + arow) * K;
    const __half* pBh = Bh + (size_t)(n0 + brow) * K + bc * 8;
    const __half* pBl = Bl + (size_t)(n0 + brow) * K + bc * 8;
    const uint32_t oA0 = tileoff(arow, acb);
    const uint32_t oA1 = tileoff(arow, acb + 1);
    const uint32_t oB  = tileoff(brow, bc);

    auto issue = [&](int chunk, uint32_t sb) {
        const int kc = chunk * 32;
        CP16(sb + oA0,           pA  + kc + acb * 8);
        CP16(sb + oA1,           pA  + kc + (acb + 1) * 8);
        CP16(sb + oB + OFF_BH,   pBh + kc);
        CP16(sb + oB + OFF_BL,   pBl + kc);
    };

    const int nk = K >> 5;           // always >= 8 here
    issue(0, sbase);                CPCOMMIT();
    issue(1, sbase + STG);          CPCOMMIT();
    issue(2, sbase + 2 * STG);      CPCOMMIT();

    int stage_c = 0;                 // stage of chunk t
    for (int t = 0; t < nk; t++) {
        if (t + 2 < nk)      { CPWAIT(2); }
        else if (t + 1 < nk) { CPWAIT(1); }
        else                 { CPWAIT(0); }
        __syncthreads();
        if (t + 3 < nk) {
            int sp = stage_c + 3; if (sp >= 4) sp -= 4;
            issue(t + 3, sbase + sp * STG);
            CPCOMMIT();
        }

        const uint32_t sb = sbase + stage_c * STG;
        #pragma unroll
        for (int ks = 0; ks < 2; ks++) {
            const int kcol = ks * 2 + (lane >> 4);
            uint32_t ar[2][4], bh4[2][4], bl4[2][4];
            #pragma unroll
            for (int mt = 0; mt < 2; mt++) {
                int row = m0w + mt * 16 + (lane & 15);
                LDSM4(ar[mt], sb + tileoff(row, kcol));
            }
            #pragma unroll
            for (int g = 0; g < 2; g++) {
                int row = n0w + g * 16 + (lane & 15);
                uint32_t a = sb + OFF_BH + tileoff(row, kcol);
                LDSM4(bh4[g], a);
                LDSM4(bl4[g], a + (OFF_BL - OFF_BH));
            }
            #pragma unroll
            for (int mt = 0; mt < 2; mt++)
                #pragma unroll
                for (int nt = 0; nt < 4; nt++) {
                    int g = nt >> 1, s = nt & 1;
                    MMA16816(acc[mt][nt], ar[mt], bh4[g][s], bh4[g][s + 2]);
                    MMA16816(acc[mt][nt], ar[mt], bl4[g][s], bl4[g][s + 2]);
                }
        }
        if (++stage_c == 4) stage_c = 0;
    }
    __syncthreads();

    // ---- epilogue stage 1: regs -> padded smem [128][65] ----
    float* ep = (float*)smc;
    {
        const int r0 = lane >> 2, cc = (lane & 3) * 2;
        #pragma unroll
        for (int mt = 0; mt < 2; mt++)
            #pragma unroll
            for (int nt = 0; nt < 4; nt++) {
                int row = m0w + mt * 16 + r0;
                int col = n0w + nt * 8 + cc;
                ep[row * 65 + col]           = acc[mt][nt][0];
                ep[row * 65 + col + 1]       = acc[mt][nt][1];
                ep[(row + 8) * 65 + col]     = acc[mt][nt][2];
                ep[(row + 8) * 65 + col + 1] = acc[mt][nt][3];
            }
    }
    __syncthreads();

    // ---- epilogue stage 2: smem -> gmem ----
    if (epi == EPI_QKV) {
        // N-tile covers exactly one head: n0 multiple of 64, HD=64
        const int sel = n0 >> 9, head = (n0 & 511) >> 6;
        float* dst = (sel == 0) ? q : (sel == 1) ? k : v;
        const int d = tid & 31;   // invariant across loop (256 % 32 == 0)
        float invf = 0.f;
        if (sel < 2) invf = powf(10000.f, -(float)d * (1.0f / 32.0f));
        for (int p = tid; p < 128 * 32; p += 256) {
            int m = p >> 5;
            int mg = m0 + m, b = mg >> 10, tt = mg & 1023;
            float v0 = ep[m * 65 + d]      + bias[n0 + d];
            float v1 = ep[m * 65 + d + 32] + bias[n0 + d + 32];
            size_t oi = (((size_t)(b * NH_ + head)) * T_ + tt) * (size_t)HD_ + d;
            if (sel < 2) {
                float ang = (float)ts[b * T_ + tt] * invf, s, c;
                sincosf(ang, &s, &c);
                dst[oi]      = v0 * c - v1 * s;
                dst[oi + 32] = v1 * c + v0 * s;
            } else {
                dst[oi] = v0; dst[oi + 32] = v1;
            }
        }
    } else {
        for (int p = tid; p < 128 * 32; p += 256) {
            int m = p >> 5, np = (p & 31) << 1;
            int mg = m0 + m, n = n0 + np;
            float v0 = ep[m * 65 + np]     + bias[n];
            float v1 = ep[m * 65 + np + 1] + bias[n + 1];
            if (epi == EPI_GELU) {
                v0 = gelu_f(v0); v1 = gelu_f(v1);
                __half2 hp; hp.x = __float2half_rn(v0); hp.y = __float2half_rn(v1);
                *(__half2*)(outh + (size_t)mg * N + n) = hp;
            } else if (epi == EPI_PLAIN) {
                float2 o; o.x = v0; o.y = v1;
                *(float2*)(outf + (size_t)mg * N + n) = o;
            } else { // EPI_RESID
                float2 rr = *(const float2*)(resid + (size_t)mg * N + n);
                float2 o; o.x = v0 + rr.x; o.y = v1 + rr.y;
                *(float2*)(outf + (size_t)mg * N + n) = o;
            }
        }
    }
}

// ---------------- LayerNorm over H=512 -> fp16 ----------------
__global__ __launch_bounds__(128) void ln_kernel(
    const float* __restrict__ x, const float* __restrict__ g,
    const float* __restrict__ b, __half* __restrict__ oh)
{
    const int r = blockIdx.x;
    const int tid = threadIdx.x;
    const float* row = x + (size_t)r * H_;
    float4 v = *(const float4*)(row + tid * 4);
    float s = v.x + v.y + v.z + v.w;
    float q = v.x * v.x + v.y * v.y + v.z * v.z + v.w * v.w;
    __shared__ float ss[128], sq[128];
    ss[tid] = s; sq[tid] = q;
    __syncthreads();
    #pragma unroll
    for (int st = 64; st > 0; st >>= 1) {
        if (tid < st) { ss[tid] += ss[tid + st]; sq[tid] += sq[tid + st]; }
        __syncthreads();
    }
    float mean = ss[0] * (1.0f / H_);
    float var  = sq[0] * (1.0f / H_) - mean * mean;
    float inv  = rsqrtf(var + 1e-5f);
    float4 gg = *(const float4*)(g + tid * 4);
    float4 bb = *(const float4*)(b + tid * 4);
    float o0 = (v.x - mean) * inv * gg.x + bb.x;
    float o1 = (v.y - mean) * inv * gg.y + bb.y;
    float o2 = (v.z - mean) * inv * gg.z + bb.z;
    float o3 = (v.w - mean) * inv * gg.w + bb.w;
    size_t o = (size_t)r * H_ + tid * 4;
    __half2 p0; p0.x = __float2half_rn(o0); p0.y = __float2half_rn(o1);
    __half2 p1; p1.x = __float2half_rn(o2); p1.y = __float2half_rn(o3);
    *(__half2*)(oh + o)     = p0;
    *(__half2*)(oh + o + 2) = p1;
}

// ---------------- Banded attention (fp32, outputs fp16) ----------------
#define TQ 64
#define SPAN 192
#define KT_STRIDE 196
#define ATTN_SMEM ((64*64 + 64*KT_STRIDE + SPAN*64 + 8*SPAN + SPAN) * 4)

__global__ __launch_bounds__(256) void attn_kernel(
    const float* __restrict__ q, const float* __restrict__ k,
    const float* __restrict__ v, const int* __restrict__ smask,
    __half* __restrict__ o_h)
{
    extern __shared__ __align__(16) float sm[];
    float* Qs = sm;                       // [64][64]
    float* Kt = Qs + 64 * 64;             // [64][KT_STRIDE] transposed K
    float* Vs = Kt + 64 * KT_STRIDE;      // [SPAN][64]
    float* Ps = Vs + SPAN * 64;           // [8 warps][SPAN]
    float* Km = Ps + 8 * SPAN;            // [SPAN] mask add

    const int tid = threadIdx.x;
    const int qb = blockIdx.x, hh = blockIdx.y, b = blockIdx.z;
    const int i0 = qb * TQ;
    const int j0 = i0 - 128;
    const float* qb_ = q + ((size_t)(b * NH_ + hh) * T_) * HD_;
    const float* kb_ = k + ((size_t)(b * NH_ + hh) * T_) * HD_;
    const float* vb_ = v + ((size_t)(b * NH_ + hh) * T_) * HD_;

    for (int idx = tid; idx < 64 * 16; idx += 256) {
        int r = idx >> 4, c4 = (idx & 15) << 2;
        *(float4*)(Qs + r * 64 + c4) =
            *(const float4*)(qb_ + (size_t)(i0 + r) * HD_ + c4);
    }
    for (int idx = tid; idx < SPAN * 16; idx += 256) {
        int r = idx >> 4, c4 = (idx & 15) << 2;
        int j = j0 + r;
        float4 kv = make_float4(0.f, 0.f, 0.f, 0.f);
        float4 vv = make_float4(0.f, 0.f, 0.f, 0.f);
        if (j >= 0) {
            kv = *(const float4*)(kb_ + (size_t)j * HD_ + c4);
            vv = *(const float4*)(vb_ + (size_t)j * HD_ + c4);
        }
        Kt[(c4 + 0) * KT_STRIDE + r] = kv.x;
        Kt[(c4 + 1) * KT_STRIDE + r] = kv.y;
        Kt[(c4 + 2) * KT_STRIDE + r] = kv.z;
        Kt[(c4 + 3) * KT_STRIDE + r] = kv.w;
        *(float4*)(Vs + r * 64 + c4) = vv;
    }
    for (int idx = tid; idx < SPAN; idx += 256) {
        int j = j0 + idx;
        Km[idx] = (j >= 0 && smask[b * T_ + j] != 0) ? 0.f : -1e30f;
    }
    __syncthreads();

    const int w = tid >> 5, l = tid & 31;
    for (int r = 0; r < 8; r++) {
        int qq = w * 8 + r;
        int i = i0 + qq;
        float s0 = 0.f, s1 = 0.f, s2 = 0.f, s3 = 0.f, s4 = 0.f, s5 = 0.f;
        const float* qrow = Qs + qq * 64;
        #pragma unroll 8
        for (int d = 0; d < 64; d++) {
            float qv = qrow[d];
            const float* kr = Kt + d * KT_STRIDE + l;
            s0 += qv * kr[0];   s1 += qv * kr[32];  s2 += qv * kr[64];
            s3 += qv * kr[96];  s4 += qv * kr[128]; s5 += qv * kr[160];
        }
        float sv[6];
        float sc[6] = {s0, s1, s2, s3, s4, s5};
        float mx = -1e30f;
        #pragma unroll
        for (int c = 0; c < 6; c++) {
            int jj = c * 32 + l;
            bool inband = (jj >= qq) && (jj <= qq + 128);
            sv[c] = inband ? (sc[c] * 0.125f + Km[jj]) : -1e30f;
            mx = fmaxf(mx, sv[c]);
        }
        #pragma unroll
        for (int st = 16; st; st >>= 1)
            mx = fmaxf(mx, __shfl_xor_sync(0xffffffffu, mx, st));
        float e[6], sum = 0.f;
        #pragma unroll
        for (int c = 0; c < 6; c++) { e[c] = __expf(sv[c] - mx); sum += e[c]; }
        #pragma unroll
        for (int st = 16; st; st >>= 1)
            sum += __shfl_xor_sync(0xffffffffu, sum, st);
        float invs = 1.0f / sum;
        #pragma unroll
        for (int c = 0; c < 6; c++)
            Ps[w * SPAN + c * 32 + l] = e[c] * invs;
        __syncwarp();

        float ax = 0.f, ay = 0.f;
        const float* pp = Ps + w * SPAN;
        const int jend = qq + 128;
        for (int jj = qq; jj <= jend; jj++) {
            float pj = pp[jj];
            float2 vv = *(const float2*)(Vs + jj * 64 + (l << 1));
            ax += pj * vv.x; ay += pj * vv.y;
        }
        size_t oi = (((size_t)b * T_ + i) * NH_ + hh) * (size_t)HD_ + (l << 1);
        __half2 hp; hp.x = __float2half_rn(ax); hp.y = __float2half_rn(ay);
        *(__half2*)(o_h + oi) = hp;
        __syncwarp();
    }
}

// ---------------- launcher ----------------
extern "C" void kernel_launch(void* const* d_in, const int* in_sizes, int n_in,
                              void* d_out, int out_size)
{
    const float* spikes   = (const float*)d_in[0];
    const int*   smask    = (const int*)  d_in[1];
    const int*   ts       = (const int*)  d_in[2];
    const float* embed_w  = (const float*)d_in[3];
    const float* embed_b  = (const float*)d_in[4];
    const float* proj_w   = (const float*)d_in[5];
    const float* proj_b   = (const float*)d_in[6];
    const float* ln1_g    = (const float*)d_in[7];
    const float* ln1_b    = (const float*)d_in[8];
    const float* Wq       = (const float*)d_in[9];
    const float* bq       = (const float*)d_in[10];
    const float* Wk       = (const float*)d_in[11];
    const float* bk       = (const float*)d_in[12];
    const float* Wv       = (const float*)d_in[13];
    const float* bv       = (const float*)d_in[14];
    const float* Wo       = (const float*)d_in[15];
    const float* bo       = (const float*)d_in[16];
    const float* ln2_g    = (const float*)d_in[17];
    const float* ln2_b    = (const float*)d_in[18];
    const float* up_w     = (const float*)d_in[19];
    const float* up_b     = (const float*)d_in[20];
    const float* down_w   = (const float*)d_in[21];
    const float* down_b   = (const float*)d_in[22];
    float* x = (float*)d_out;

    __half *wth, *wtl, *sp, *e, *h, *o, *u;
    float *qp, *kp, *vp, *qkvb;
    cudaGetSymbolAddress((void**)&wth, g_wth);
    cudaGetSymbolAddress((void**)&wtl, g_wtl);
    cudaGetSymbolAddress((void**)&sp,  g_sp);
    cudaGetSymbolAddress((void**)&e,   g_e);
    cudaGetSymbolAddress((void**)&h,   g_h);
    cudaGetSymbolAddress((void**)&o,   g_o);
    cudaGetSymbolAddress((void**)&u,   g_u);
    cudaGetSymbolAddress((void**)&qp,  g_q);
    cudaGetSymbolAddress((void**)&kp,  g_k);
    cudaGetSymbolAddress((void**)&vp,  g_v);
    cudaGetSymbolAddress((void**)&qkvb, g_qkvb);

    cudaFuncSetAttribute(attn_kernel,
        cudaFuncAttributeMaxDynamicSharedMemorySize, ATTN_SMEM);
    cudaFuncSetAttribute(hmma_gemm,
        cudaFuncAttributeMaxDynamicSharedMemorySize, GEMM_SMEM);

    // ---- preamble: 2 launches ----
    transpose_split_all<<<dim3(1024, 27), 256>>>(
        embed_w, proj_w, Wq, Wk, Wv, Wo, up_w, down_w, bq, bk, bv,
        wth, wtl, qkvb);
    tohalf_kernel<<<(M_ * C_ + 255) / 256, 256>>>(spikes, sp, M_ * C_);

    // ---- embed: e = gelu(spikes @ embed_w + b) -> fp16 ----
    hmma_gemm<<<dim3(D_/64, M_/128), 256, GEMM_SMEM>>>(
        sp, wth + OFF_EMB, wtl + OFF_EMB, embed_b, nullptr, nullptr,
        nullptr, e, nullptr, nullptr, nullptr, D_, C_, EPI_GELU);
    // ---- x = e @ proj_w + b ----
    hmma_gemm<<<dim3(H_/64, M_/128), 256, GEMM_SMEM>>>(
        e, wth + OFF_PROJ, wtl + OFF_PROJ, proj_b, nullptr, nullptr,
        x, nullptr, nullptr, nullptr, nullptr, H_, D_, EPI_PLAIN);

    for (int l = 0; l < L_; l++) {
        ln_kernel<<<M_, 128>>>(x, ln1_g + l * H_, ln1_b + l * H_, h);
        // fused QKV + RoPE: B = [Wq^T; Wk^T; Wv^T]  (N = 1536)
        hmma_gemm<<<dim3(1536/64, M_/128), 256, GEMM_SMEM>>>(
            h, wth + OFF_QKV(l), wtl + OFF_QKV(l), qkvb + l * 1536, nullptr, ts,
            nullptr, nullptr, qp, kp, vp, 1536, H_, EPI_QKV);
        attn_kernel<<<dim3(T_ / TQ, NH_, B_), 256, ATTN_SMEM>>>(qp, kp, vp, smask, o);
        hmma_gemm<<<dim3(H_/64, M_/128), 256, GEMM_SMEM>>>(
            o, wth + OFF_O(l), wtl + OFF_O(l), bo + l * H_, x, nullptr,
            x, nullptr, nullptr, nullptr, nullptr, H_, H_, EPI_RESID);
        ln_kernel<<<M_, 128>>>(x, ln2_g + l * H_, ln2_b + l * H_, h);
        hmma_gemm<<<dim3(INTER_/64, M_/128), 256, GEMM_SMEM>>>(
            h, wth + OFF_UP(l), wtl + OFF_UP(l), up_b + l * INTER_, nullptr, nullptr,
            nullptr, u, nullptr, nullptr, nullptr, INTER_, H_, EPI_GELU);
        hmma_gemm<<<dim3(H_/64, M_/128), 256, GEMM_SMEM>>>(
            u, wth + OFF_DOWN(l), wtl + OFF_DOWN(l), down_b + l * H_, x, nullptr,
            x, nullptr, nullptr, nullptr, nullptr, H_, INTER_, EPI_RESID);
    }
}